// round 15
// baseline (speedup 1.0000x reference)
#include <cuda_runtime.h>
#include <cuda_bf16.h>
#include <math.h>
#include <stdint.h>

#define NB 8
#define C 256
#define HW 1024
#define HIDDEN 1024

__device__ float g_qbranch[NB*C*HW];
__device__ float g_kvbranch[NB*C*HW];
__device__ float g_h1[NB*HIDDEN*HW];
__device__ float g_h2[NB*HIDDEN*HW];            // reused as bf16 tokmaj planes after dwconv
__device__ __align__(256) __nv_bfloat16 g_wbf[7100000];
__device__ __align__(256) __nv_bfloat16 g_bln[4194304];
__device__ __align__(256) __nv_bfloat16 g_bqk[8388608];
__device__ __align__(256) __nv_bfloat16 g_bv[4194304];
__device__ __align__(256) __nv_bfloat16 g_batt[4194304];

#define WC3    0
#define SP3    589824
#define WC5    1179648
#define SP5    1638400
#define WSAQ   4456448
#define SPQKV  196608
#define WSAKV  4849664
#define WSAQP  5242880
#define SPCC   65536
#define WSAKVP 5373952
#define WCAQ   5505024
#define WCAKV  5636096
#define SPKV   131072
#define WCAP   5898240
#define WLIN   6029312
#define SPLF   262144
#define WLOUT  6553600

// ---------------- helpers ----------------
__device__ __forceinline__ uint32_t smem_u32(const void* p) {
    uint32_t a;
    asm("{ .reg .u64 t; cvta.to.shared.u64 t, %1; cvt.u32.u64 %0, t; }" : "=r"(a) : "l"(p));
    return a;
}
__device__ __forceinline__ void cp16(void* dst, const void* src) {
    unsigned d = (unsigned)__cvta_generic_to_shared(dst);
    asm volatile("cp.async.ca.shared.global [%0], [%1], 16;" :: "r"(d), "l"(src));
}
__device__ __forceinline__ void cp_commit() { asm volatile("cp.async.commit_group;" ::: "memory"); }
__device__ __forceinline__ void cp_wait0()  { asm volatile("cp.async.wait_group 0;" ::: "memory"); }

__device__ __forceinline__ void ldmx4(uint32_t* r, uint32_t addr) {
    asm volatile("ldmatrix.sync.aligned.m8n8.x4.shared.b16 {%0,%1,%2,%3}, [%4];"
        : "=r"(r[0]), "=r"(r[1]), "=r"(r[2]), "=r"(r[3]) : "r"(addr));
}
__device__ __forceinline__ void mma16816(float* c, const uint32_t* a, const uint32_t* b) {
    asm volatile("mma.sync.aligned.m16n8k16.row.col.f32.bf16.bf16.f32 "
        "{%0,%1,%2,%3}, {%4,%5,%6,%7}, {%8,%9}, {%0,%1,%2,%3};"
        : "+f"(c[0]), "+f"(c[1]), "+f"(c[2]), "+f"(c[3])
        : "r"(a[0]), "r"(a[1]), "r"(a[2]), "r"(a[3]), "r"(b[0]), "r"(b[1]));
}
__device__ __forceinline__ unsigned pkbf(float a, float b) {
    __nv_bfloat16 ha = __float2bfloat16(a), hb = __float2bfloat16(b);
    return ((unsigned)__bfloat16_as_ushort(hb) << 16) | __bfloat16_as_ushort(ha);
}
__device__ __forceinline__ void splitpk(float a, float b, unsigned& hi, unsigned& lo) {
    __nv_bfloat16 ha = __float2bfloat16(a), hb = __float2bfloat16(b);
    hi = ((unsigned)__bfloat16_as_ushort(hb) << 16) | __bfloat16_as_ushort(ha);
    lo = pkbf(a - __bfloat162float(ha), b - __bfloat162float(hb));
}

// =====================================================================
// mma.sync GEMM / implicit conv. Tile 128(pix) x 64(oc), 2 CTAs/SM.
// stage (48K): AH 16K | AL 16K | BH 8K | BL 8K. 2 stages = 96K.
// ABF=0: act fp32 chanmaj (KW taps); ABF=1: pre-split bf16 tokmaj.
// outmode 0: fp32 chanmaj (+addp); 1: bf16 tokmaj; 2: bf16 chanmaj;
// 3: y<ysplit -> tokmaj, else chanmaj (ocb=(y-ysplit)*64)
// =====================================================================
#define STG 49152
template<int KW, int PAD, int ABF>
__global__ __launch_bounds__(256, 2) void mm_tc(
    const __nv_bfloat16* __restrict__ whi, const __nv_bfloat16* __restrict__ wlo,
    const float* __restrict__ act,
    const __nv_bfloat16* __restrict__ ahi, const __nv_bfloat16* __restrict__ alo, int arow,
    float* __restrict__ outp, const float* __restrict__ addp,
    __nv_bfloat16* __restrict__ obhi, __nv_bfloat16* __restrict__ oblo,
    __nv_bfloat16* __restrict__ vbhi, __nv_bfloat16* __restrict__ vblo,
    int K, int SA, int Cout, int outmode, int ysplit)
{
    extern __shared__ char sm[];
    int tid = threadIdx.x;
    int pixbase = blockIdx.x * 128;
    int ocbase = blockIdx.y * 64;
    int bimg = blockIdx.z;
    int w = tid >> 5, lane = tid & 31;
    int m0 = (w >> 1) * 32;
    int n0 = (w & 1) * 32;
    uint32_t sbase = smem_u32(sm);

    float acc[2][4][4] = {};
    int apix = tid & 127, ahalf = tid >> 7;

    auto fetchA = [&](int kk, float* v) {
        if (KW == 0) {
            const float* p = act + ((size_t)bimg * SA + kk + ahalf * 32) * 1024 + pixbase + apix;
            #pragma unroll
            for (int i = 0; i < 32; i++) v[i] = p[(size_t)i * 1024];
        } else {
            int kbase = kk + ahalf * 32;
            int tap = kbase >> 8, ic0 = kbase & 255;
            int dy = tap / KW - PAD, dx = tap % KW - PAD;
            int p = pixbase + apix;
            int iy = (p >> 5) + dy, ix = (p & 31) + dx;
            bool ok = ((unsigned)iy < 32u) && ((unsigned)ix < 32u);
            const float* src = act + ((size_t)bimg * 256 + ic0) * 1024 + (iy << 5) + ix;
            #pragma unroll
            for (int i = 0; i < 32; i++) v[i] = ok ? src[(size_t)i * 1024] : 0.f;
        }
    };
    auto storeA = [&](int st, const float* v) {
        char* AH = sm + st * STG;
        char* AL = AH + 16384;
        #pragma unroll
        for (int gi = 0; gi < 4; gi++) {
            int g = ahalf * 4 + gi;
            unsigned hh[4], ll[4];
            #pragma unroll
            for (int m = 0; m < 4; m++)
                splitpk(v[gi * 8 + 2 * m], v[gi * 8 + 2 * m + 1], hh[m], ll[m]);
            unsigned off = apix * 128 + ((g ^ (apix & 7)) << 4);
            *(uint4*)(AH + off) = make_uint4(hh[0], hh[1], hh[2], hh[3]);
            *(uint4*)(AL + off) = make_uint4(ll[0], ll[1], ll[2], ll[3]);
        }
    };
    auto loadAbf = [&](int st, int kk) {
        char* base = sm + st * STG;
        #pragma unroll
        for (int i = 0; i < 8; i++) {
            int idx = tid + i * 256;
            int plane = idx >> 10, r = idx & 1023;
            int pix = r >> 3, g = r & 7;
            const __nv_bfloat16* src = (plane ? alo : ahi)
                + ((size_t)bimg * 1024 + pixbase + pix) * arow + kk + g * 8;
            unsigned off = pix * 128 + ((g ^ (pix & 7)) << 4);
            cp16(base + plane * 16384 + off, src);
        }
    };
    auto loadB = [&](int st, int kk) {
        char* base = sm + st * STG + 32768;
        #pragma unroll
        for (int i = 0; i < 4; i++) {
            int idx = tid + i * 256;
            int plane = idx >> 9, r = idx & 511;
            int oc = r >> 3, g = r & 7;
            const __nv_bfloat16* src = (plane ? wlo : whi) + (size_t)(ocbase + oc) * K + kk + g * 8;
            unsigned off = oc * 128 + ((g ^ (oc & 7)) << 4);
            cp16(base + plane * 8192 + off, src);
        }
    };
    auto compute = [&](int st) {
        uint32_t AH = sbase + st * STG, AL = AH + 16384;
        uint32_t BH = AH + 32768, BL = AH + 40960;
        #pragma unroll
        for (int ks = 0; ks < 4; ks++) {
            int kg = ks * 2;
            uint32_t aH[2][4], aL[2][4], bH[4][2], bL[4][2];
            #pragma unroll
            for (int ms = 0; ms < 2; ms++) {
                int sel = lane >> 3;
                int row = m0 + ms * 16 + (sel & 1) * 8 + (lane & 7);
                int g = kg + (sel >> 1);
                unsigned off = row * 128 + ((g ^ (row & 7)) << 4);
                ldmx4(aH[ms], AH + off);
                ldmx4(aL[ms], AL + off);
            }
            #pragma unroll
            for (int nj = 0; nj < 2; nj++) {
                int j2 = lane >> 4, half = (lane >> 3) & 1;
                int oc = n0 + (nj * 2 + j2) * 8 + (lane & 7);
                int g = kg + half;
                unsigned off = oc * 128 + ((g ^ (oc & 7)) << 4);
                uint32_t t[4];
                ldmx4(t, BH + off);
                bH[nj*2][0] = t[0]; bH[nj*2][1] = t[1]; bH[nj*2+1][0] = t[2]; bH[nj*2+1][1] = t[3];
                ldmx4(t, BL + off);
                bL[nj*2][0] = t[0]; bL[nj*2][1] = t[1]; bL[nj*2+1][0] = t[2]; bL[nj*2+1][1] = t[3];
            }
            #pragma unroll
            for (int ms = 0; ms < 2; ms++)
                #pragma unroll
                for (int ns = 0; ns < 4; ns++) {
                    mma16816(acc[ms][ns], aH[ms], bH[ns]);
                    mma16816(acc[ms][ns], aH[ms], bL[ns]);
                    mma16816(acc[ms][ns], aL[ms], bH[ns]);
                }
        }
    };

    int nk = K >> 6;
    if (ABF) {
        loadB(0, 0); loadAbf(0, 0);
        cp_commit();
        cp_wait0();
        __syncthreads();
        for (int kt = 0; kt < nk; kt++) {
            int st = kt & 1;
            bool more = (kt + 1) < nk;
            if (more) {
                loadB(st ^ 1, (kt + 1) << 6);
                loadAbf(st ^ 1, (kt + 1) << 6);
                cp_commit();
            }
            compute(st);
            if (more) cp_wait0();
            __syncthreads();
        }
    } else {
        float v[32];
        loadB(0, 0); cp_commit();
        fetchA(0, v); storeA(0, v);
        cp_wait0();
        __syncthreads();
        for (int kt = 0; kt < nk; kt++) {
            int st = kt & 1;
            bool more = (kt + 1) < nk;
            if (more) {
                loadB(st ^ 1, (kt + 1) << 6); cp_commit();
                fetchA((kt + 1) << 6, v);
            }
            compute(st);
            if (more) {
                storeA(st ^ 1, v);
                cp_wait0();
            }
            __syncthreads();
        }
    }

    // output-mode resolution
    int outm = outmode;
    int ocb = ocbase;
    __nv_bfloat16 *ph = obhi, *pl = oblo;
    if (outmode == 3) {
        if ((int)blockIdx.y < ysplit) outm = 1;
        else { outm = 2; ph = vbhi; pl = vblo; ocb = (blockIdx.y - ysplit) * 64; }
    }

    float* T = (float*)sm;
    if (outm == 1) {
        // T[pix][68], pix 0..127, oc 0..63
        #pragma unroll
        for (int ms = 0; ms < 2; ms++)
            #pragma unroll
            for (int ns = 0; ns < 4; ns++)
                #pragma unroll
                for (int e = 0; e < 4; e++) {
                    int pix = m0 + ms * 16 + (lane >> 2) + (e >> 1) * 8;
                    int oc  = n0 + ns * 8 + (lane & 3) * 2 + (e & 1);
                    T[pix * 68 + oc] = acc[ms][ns][e];
                }
        __syncthreads();
        #pragma unroll
        for (int it = 0; it < 8; it++) {
            int f = it * 256 + tid;
            int pix = f >> 4, o4 = (f & 15) * 4;
            float4 vv = *(float4*)&T[pix * 68 + o4];
            unsigned h0, l0, h1, l1;
            splitpk(vv.x, vv.y, h0, l0);
            splitpk(vv.z, vv.w, h1, l1);
            size_t idx = ((size_t)bimg * 1024 + pixbase + pix) * Cout + ocbase + o4;
            *(uint2*)(ph + idx) = make_uint2(h0, h1);
            *(uint2*)(pl + idx) = make_uint2(l0, l1);
        }
    } else {
        // T[oc][132], oc 0..63, pix 0..127
        #pragma unroll
        for (int ms = 0; ms < 2; ms++)
            #pragma unroll
            for (int ns = 0; ns < 4; ns++)
                #pragma unroll
                for (int e = 0; e < 4; e++) {
                    int pix = m0 + ms * 16 + (lane >> 2) + (e >> 1) * 8;
                    int oc  = n0 + ns * 8 + (lane & 3) * 2 + (e & 1);
                    T[oc * 132 + pix] = acc[ms][ns][e];
                }
        __syncthreads();
        #pragma unroll
        for (int it = 0; it < 8; it++) {
            int f = it * 256 + tid;
            int oc = f >> 5, p4 = (f & 31) * 4;
            float4 vv = *(float4*)&T[oc * 132 + p4];
            if (outm == 0) {
                size_t go = ((size_t)bimg * Cout + ocb + oc) * 1024 + pixbase + p4;
                if (addp) {
                    float4 a = *(const float4*)(addp + go);
                    vv.x += a.x; vv.y += a.y; vv.z += a.z; vv.w += a.w;
                }
                *(float4*)(outp + go) = vv;
            } else {
                unsigned h0, l0, h1, l1;
                splitpk(vv.x, vv.y, h0, l0);
                splitpk(vv.z, vv.w, h1, l1);
                size_t idx = ((size_t)bimg * 256 + ocb + oc) * 1024 + pixbase + p4;
                *(uint2*)(ph + idx) = make_uint2(h0, h1);
                *(uint2*)(pl + idx) = make_uint2(l0, l1);
            }
        }
    }
}

// ---------------- fused weight prep ----------------
__global__ __launch_bounds__(256) void prep_w(
    __nv_bfloat16* __restrict__ wb,
    const float* w3, const float* w5,
    const float* saqk, const float* sakvk,
    const float* saqp, const float* sakvp,
    const float* caq, const float* cak, const float* cav, const float* cap,
    const float* lin, const float* lout)
{
    int i = blockIdx.x * 256 + threadIdx.x;
    float v; size_t dh, dl;
    if (i < 589824) {
        int j = i;
        int oc = j / (9*256); int r = j - oc*9*256; int tap = r >> 8, ic = r & 255;
        v = w3[((size_t)(oc*256+ic))*9 + tap]; dh = WC3 + j; dl = dh + SP3;
    } else if (i < 2228224) {
        int j = i - 589824;
        int oc = j / (25*256); int r = j - oc*25*256; int tap = r >> 8, ic = r & 255;
        v = w5[((size_t)(oc*256+ic))*25 + tap]; dh = WC5 + j; dl = dh + SP5;
    } else if (i < 2424832) { int j = i - 2228224; v = saqk[j];  dh = WSAQ + j;  dl = dh + SPQKV; }
    else if (i < 2621440) { int j = i - 2424832; v = sakvk[j]; dh = WSAKV + j; dl = dh + SPQKV; }
    else if (i < 2686976) { int j = i - 2621440; v = saqp[j];  dh = WSAQP + j; dl = dh + SPCC; }
    else if (i < 2752512) { int j = i - 2686976; v = sakvp[j]; dh = WSAKVP + j; dl = dh + SPCC; }
    else if (i < 2818048) { int j = i - 2752512; v = caq[j];   dh = WCAQ + j;  dl = dh + SPCC; }
    else if (i < 2883584) { int j = i - 2818048; v = cak[j];   dh = WCAKV + j; dl = dh + SPKV; }
    else if (i < 2949120) { int j = i - 2883584; v = cav[j];   dh = WCAKV + 65536 + j; dl = dh + SPKV; }
    else if (i < 3014656) { int j = i - 2949120; v = cap[j];   dh = WCAP + j;  dl = dh + SPCC; }
    else if (i < 3276800) { int j = i - 3014656; v = lin[j];   dh = WLIN + j;  dl = dh + SPLF; }
    else if (i < 3538944) { int j = i - 3276800; v = lout[j];  dh = WLOUT + j; dl = dh + SPLF; }
    else return;
    __nv_bfloat16 h = __float2bfloat16(v);
    wb[dh] = h;
    wb[dl] = __float2bfloat16(v - __bfloat162float(h));
}

// ---------------- layernorm: chanmaj fp32 -> tokmaj bf16 hi/lo ----------------
__global__ __launch_bounds__(256) void ln_kernel(
    const float* __restrict__ x, const float* __restrict__ w,
    const float* __restrict__ bias,
    __nv_bfloat16* __restrict__ bhi, __nv_bfloat16* __restrict__ blo)
{
    int b = blockIdx.y;
    int n0 = blockIdx.x * 32;
    int nx = threadIdx.x & 31;
    int cg = threadIdx.x >> 5;
    const float* xb = x + (size_t)b * C * HW + n0 + nx;
    float v[32];
    float s = 0.f, ss = 0.f;
    #pragma unroll
    for (int i = 0; i < 32; i++) {
        float t = xb[(size_t)(cg * 32 + i) * HW];
        v[i] = t; s += t; ss += t * t;
    }
    __shared__ float rs[8][32], rss[8][32];
    rs[cg][nx] = s; rss[cg][nx] = ss;
    __syncthreads();
    float tot = 0.f, tot2 = 0.f;
    #pragma unroll
    for (int g = 0; g < 8; g++) { tot += rs[g][nx]; tot2 += rss[g][nx]; }
    float mu = tot * (1.f / 256.f);
    float var = tot2 * (1.f / 256.f) - mu * mu;
    float rstd = rsqrtf(var + 1e-5f);
    size_t orow = ((size_t)b * 1024 + n0 + nx) * 256 + cg * 32;
    #pragma unroll
    for (int i4 = 0; i4 < 4; i4++) {
        unsigned hh[4], ll[4];
        #pragma unroll
        for (int j = 0; j < 4; j++) {
            int i = i4 * 8 + j * 2;
            int c = cg * 32 + i;
            float a = (v[i]   - mu) * rstd * w[c]   + bias[c];
            float d = (v[i+1] - mu) * rstd * w[c+1] + bias[c+1];
            splitpk(a, d, hh[j], ll[j]);
        }
        *(uint4*)(bhi + orow + i4 * 8) = make_uint4(hh[0], hh[1], hh[2], hh[3]);
        *(uint4*)(blo + orow + i4 * 8) = make_uint4(ll[0], ll[1], ll[2], ll[3]);
    }
}

// ---------------- tensor-core flash attention (pre-split bf16) ----------------
__global__ __launch_bounds__(128) void attn_mma(
    const __nv_bfloat16* __restrict__ qhi, const __nv_bfloat16* __restrict__ qlo, int qrow,
    const __nv_bfloat16* __restrict__ khi, const __nv_bfloat16* __restrict__ klo, int krow,
    const __nv_bfloat16* __restrict__ vhi, const __nv_bfloat16* __restrict__ vlo,
    __nv_bfloat16* __restrict__ ohi, __nv_bfloat16* __restrict__ olo)
{
    extern __shared__ char sm[];
    uint32_t sbase = smem_u32(sm);
    int tid = threadIdx.x;
    int w = tid >> 5, lane = tid & 31;
    int q0 = blockIdx.x * 64;
    int hoff = blockIdx.y * 64;
    int bimg = blockIdx.z;
    int m0 = w * 16;

    auto loadQ = [&]() {
        #pragma unroll
        for (int i = 0; i < 8; i++) {
            int idx = tid + i * 128;
            int plane = idx >> 9, r = idx & 511;
            int q = r >> 3, g = r & 7;
            const __nv_bfloat16* src = (plane ? qlo : qhi)
                + ((size_t)bimg * 1024 + q0 + q) * qrow + hoff + g * 8;
            unsigned off = q * 128 + ((g ^ (q & 7)) << 4);
            cp16(sm + plane * 8192 + off, src);
        }
    };
    auto loadKV = [&](int st, int c0) {
        char* base = sm + 16384 + st * 32768;
        #pragma unroll
        for (int i = 0; i < 16; i++) {
            int idx = tid + i * 128;
            int which = idx >> 10;
            int plane = (idx >> 9) & 1;
            int r = idx & 511;
            int row = r >> 3, g = r & 7;
            const __nv_bfloat16* src;
            if (which == 0)
                src = (plane ? klo : khi) + ((size_t)bimg * 1024 + c0 + row) * krow + hoff + g * 8;
            else
                src = (plane ? vlo : vhi) + ((size_t)bimg * 256 + hoff + row) * 1024 + c0 + g * 8;
            unsigned off = row * 128 + ((g ^ (row & 7)) << 4);
            cp16(base + which * 16384 + plane * 8192 + off, src);
        }
    };

    loadQ();
    loadKV(0, 0);
    cp_commit();

    float oacc[8][4] = {};
    float mrun[2], lrun[2];
    mrun[0] = mrun[1] = -1e30f;
    lrun[0] = lrun[1] = 0.f;

    cp_wait0();
    __syncthreads();

    const uint32_t QH = sbase, QL = sbase + 8192;
    for (int c = 0; c < 16; c++) {
        int st = c & 1;
        bool more = (c + 1) < 16;
        if (more) { loadKV(st ^ 1, (c + 1) * 64); cp_commit(); }

        uint32_t KB = sbase + 16384 + st * 32768;
        uint32_t KH = KB, KL = KB + 8192, VH = KB + 16384, VL = KB + 24576;

        float s[8][4] = {};
        #pragma unroll
        for (int ks4 = 0; ks4 < 4; ks4++) {
            int kg = ks4 * 2;
            uint32_t aH[4], aL[4];
            {
                int sel = lane >> 3;
                int row = m0 + (sel & 1) * 8 + (lane & 7);
                int g = kg + (sel >> 1);
                unsigned off = row * 128 + ((g ^ (row & 7)) << 4);
                ldmx4(aH, QH + off);
                ldmx4(aL, QL + off);
            }
            #pragma unroll
            for (int nj = 0; nj < 4; nj++) {
                int j2 = lane >> 4, half = (lane >> 3) & 1;
                int kv = (nj * 2 + j2) * 8 + (lane & 7);
                int g = kg + half;
                unsigned off = kv * 128 + ((g ^ (kv & 7)) << 4);
                uint32_t t[4], bh0[2], bh1[2], bl0[2], bl1[2];
                ldmx4(t, KH + off);
                bh0[0] = t[0]; bh0[1] = t[1]; bh1[0] = t[2]; bh1[1] = t[3];
                ldmx4(t, KL + off);
                bl0[0] = t[0]; bl0[1] = t[1]; bl1[0] = t[2]; bl1[1] = t[3];
                mma16816(s[nj*2], aH, bh0);   mma16816(s[nj*2+1], aH, bh1);
                mma16816(s[nj*2], aH, bl0);   mma16816(s[nj*2+1], aH, bl1);
                mma16816(s[nj*2], aL, bh0);   mma16816(s[nj*2+1], aL, bh1);
            }
        }
        #pragma unroll
        for (int e = 0; e < 8; e++)
            #pragma unroll
            for (int j = 0; j < 4; j++) s[e][j] *= 0.125f;

        #pragma unroll
        for (int r = 0; r < 2; r++) {
            int e0 = r * 2;
            float mx = -1e30f;
            #pragma unroll
            for (int e = 0; e < 8; e++)
                mx = fmaxf(mx, fmaxf(s[e][e0], s[e][e0+1]));
            mx = fmaxf(mx, __shfl_xor_sync(0xffffffffu, mx, 1));
            mx = fmaxf(mx, __shfl_xor_sync(0xffffffffu, mx, 2));
            float mnew = fmaxf(mrun[r], mx);
            float corr = __expf(mrun[r] - mnew);
            float rsum = 0.f;
            #pragma unroll
            for (int e = 0; e < 8; e++) {
                float p0 = __expf(s[e][e0] - mnew);
                float p1 = __expf(s[e][e0+1] - mnew);
                s[e][e0] = p0; s[e][e0+1] = p1;
                rsum += p0 + p1;
            }
            rsum += __shfl_xor_sync(0xffffffffu, rsum, 1);
            rsum += __shfl_xor_sync(0xffffffffu, rsum, 2);
            lrun[r] = lrun[r] * corr + rsum;
            mrun[r] = mnew;
            #pragma unroll
            for (int e = 0; e < 8; e++) {
                oacc[e][e0] *= corr; oacc[e][e0+1] *= corr;
            }
        }

        #pragma unroll
        for (int ks4 = 0; ks4 < 4; ks4++) {
            int e = ks4 * 2;
            uint32_t aPh[4], aPl[4];
            splitpk(s[e][0],   s[e][1],   aPh[0], aPl[0]);
            splitpk(s[e][2],   s[e][3],   aPh[1], aPl[1]);
            splitpk(s[e+1][0], s[e+1][1], aPh[2], aPl[2]);
            splitpk(s[e+1][2], s[e+1][3], aPh[3], aPl[3]);
            int kg = ks4 * 2;
            #pragma unroll
            for (int nj = 0; nj < 4; nj++) {
                int j2 = lane >> 4, half = (lane >> 3) & 1;
                int d = (nj * 2 + j2) * 8 + (lane & 7);
                int g = kg + half;
                unsigned off = d * 128 + ((g ^ (d & 7)) << 4);
                uint32_t t[4], bh0[2], bh1[2], bl0[2], bl1[2];
                ldmx4(t, VH + off);
                bh0[0] = t[0]; bh0[1] = t[1]; bh1[0] = t[2]; bh1[1] = t[3];
                ldmx4(t, VL + off);
                bl0[0] = t[0]; bl0[1] = t[1]; bl1[0] = t[2]; bl1[1] = t[3];
                mma16816(oacc[nj*2], aPh, bh0);   mma16816(oacc[nj*2+1], aPh, bh1);
                mma16816(oacc[nj*2], aPh, bl0);   mma16816(oacc[nj*2+1], aPh, bl1);
                mma16816(oacc[nj*2], aPl, bh0);   mma16816(oacc[nj*2+1], aPl, bh1);
            }
        }
        if (more) cp_wait0();
        __syncthreads();
    }

    float li[2] = {1.f / lrun[0], 1.f / lrun[1]};
    #pragma unroll
    for (int nt = 0; nt < 8; nt++)
        #pragma unroll
        for (int r = 0; r < 2; r++) {
            int q = m0 + (lane >> 2) + r * 8;
            int d0 = nt * 8 + (lane & 3) * 2;
            unsigned hi, lo;
            splitpk(oacc[nt][2*r] * li[r], oacc[nt][2*r+1] * li[r], hi, lo);
            size_t idx = ((size_t)bimg * 1024 + q0 + q) * 256 + hoff + d0;
            *(unsigned*)(ohi + idx) = hi;
            *(unsigned*)(olo + idx) = lo;
        }
}

// ---------------- depthwise 3x3 + GELU -> tokmaj bf16 hi/lo ----------------
__global__ __launch_bounds__(256) void dwconv_gelu_tok(
    const float* __restrict__ X, const float* __restrict__ W,
    __nv_bfloat16* __restrict__ bhi, __nv_bfloat16* __restrict__ blo)
{
    __shared__ float tile[32][10][32];
    __shared__ float wsm[32][9];
    int tid = threadIdx.x;
    int p0 = blockIdx.x * 256;
    int c0 = blockIdx.y * 32;
    int b = blockIdx.z;
    int r0 = p0 >> 5;

    for (int e = tid; e < 288; e += 256) {
        int c = e / 9, k = e - c * 9;
        wsm[c][k] = W[(size_t)(c0 + c) * 9 + k];
    }
    for (int e = tid; e < 32 * 10 * 32; e += 256) {
        int c = e / 320, rr = e - c * 320;
        int lr = rr >> 5, col = rr & 31;
        int gr = r0 + lr - 1;
        tile[c][lr][col] = ((unsigned)gr < 32u)
            ? X[((size_t)(b * 1024 + c0 + c)) * 1024 + (gr << 5) + col] : 0.f;
    }
    __syncthreads();

    int p = p0 + tid;
    int ly = (p >> 5) - r0 + 1;
    int x = p & 31;
    unsigned hh[16], ll[16];
    float prev = 0.f;
    #pragma unroll
    for (int c = 0; c < 32; c++) {
        float acc = 0.f;
        #pragma unroll
        for (int dy = 0; dy < 3; dy++) {
            #pragma unroll
            for (int dx = 0; dx < 3; dx++) {
                int ix = x + dx - 1;
                float vv = ((unsigned)ix < 32u) ? tile[c][ly + dy - 1][ix] : 0.f;
                acc += wsm[c][dy * 3 + dx] * vv;
            }
        }
        float g = 0.5f * acc * (1.f + erff(acc * 0.70710678118654752440f));
        if (c & 1) splitpk(prev, g, hh[c >> 1], ll[c >> 1]);
        prev = g;
    }
    size_t orow = ((size_t)b * 1024 + p) * 1024 + c0;
    #pragma unroll
    for (int q = 0; q < 4; q++) {
        *(uint4*)(bhi + orow + q * 8) = make_uint4(hh[q*4], hh[q*4+1], hh[q*4+2], hh[q*4+3]);
        *(uint4*)(blo + orow + q * 8) = make_uint4(ll[q*4], ll[q*4+1], ll[q*4+2], ll[q*4+3]);
    }
}

// ---------------- host ----------------
extern "C" void kernel_launch(void* const* d_in, const int* in_sizes, int n_in,
                              void* d_out, int out_size)
{
    const float* aop      = (const float*)d_in[0];
    const float* dop      = (const float*)d_in[1];
    const float* w_qconv  = (const float*)d_in[2];
    const float* w_kvconv = (const float*)d_in[3];
    const float* lnq1_w   = (const float*)d_in[4];
    const float* lnq1_b   = (const float*)d_in[5];
    const float* lnkv1_w  = (const float*)d_in[6];
    const float* lnkv1_b  = (const float*)d_in[7];
    const float* lnq2_w   = (const float*)d_in[8];
    const float* lnq2_b   = (const float*)d_in[9];
    const float* lnkv2_w  = (const float*)d_in[10];
    const float* lnkv2_b  = (const float*)d_in[11];
    const float* lnffn_w  = (const float*)d_in[12];
    const float* lnffn_b  = (const float*)d_in[13];
    const float* saq_qkv  = (const float*)d_in[14];
    const float* saq_proj = (const float*)d_in[15];
    const float* sakv_qkv = (const float*)d_in[16];
    const float* sakv_proj= (const float*)d_in[17];
    const float* ca_q     = (const float*)d_in[18];
    const float* ca_k     = (const float*)d_in[19];
    const float* ca_v     = (const float*)d_in[20];
    const float* ca_proj  = (const float*)d_in[21];
    const float* leff_in  = (const float*)d_in[22];
    const float* leff_dw  = (const float*)d_in[23];
    const float* leff_out = (const float*)d_in[24];
    float* out = (float*)d_out;

    float *qbr, *kvbr, *h1, *h2;
    __nv_bfloat16 *wbf, *bln, *bqk, *bv, *batt;
    cudaGetSymbolAddress((void**)&qbr,  g_qbranch);
    cudaGetSymbolAddress((void**)&kvbr, g_kvbranch);
    cudaGetSymbolAddress((void**)&h1,   g_h1);
    cudaGetSymbolAddress((void**)&h2,   g_h2);
    cudaGetSymbolAddress((void**)&wbf,  g_wbf);
    cudaGetSymbolAddress((void**)&bln,  g_bln);
    cudaGetSymbolAddress((void**)&bqk,  g_bqk);
    cudaGetSymbolAddress((void**)&bv,   g_bv);
    cudaGetSymbolAddress((void**)&batt, g_batt);

    __nv_bfloat16 *blnh = bln, *blnl = bln + 2097152;
    __nv_bfloat16 *bvh = bv, *bvl = bv + 2097152;
    __nv_bfloat16 *batth = batt, *battl = batt + 2097152;
    __nv_bfloat16 *dwh = (__nv_bfloat16*)h2, *dwl = (__nv_bfloat16*)h2 + 8388608;

    const int MM_SMEM = 98304;
    const int ATT_SMEM = 81920;
    cudaFuncSetAttribute(attn_mma, cudaFuncAttributeMaxDynamicSharedMemorySize, ATT_SMEM);
    cudaFuncSetAttribute(mm_tc<0,0,0>, cudaFuncAttributeMaxDynamicSharedMemorySize, MM_SMEM);
    cudaFuncSetAttribute(mm_tc<0,0,1>, cudaFuncAttributeMaxDynamicSharedMemorySize, MM_SMEM);
    cudaFuncSetAttribute(mm_tc<3,1,0>, cudaFuncAttributeMaxDynamicSharedMemorySize, MM_SMEM);
    cudaFuncSetAttribute(mm_tc<5,2,0>, cudaFuncAttributeMaxDynamicSharedMemorySize, MM_SMEM);

    prep_w<<<13824, 256>>>(wbf, w_qconv, w_kvconv, saq_qkv, sakv_qkv, saq_proj, sakv_proj,
                           ca_q, ca_k, ca_v, ca_proj, leff_in, leff_out);

    // grids: y = Cout/64 tiles
    dim3 gC(8, 4, NB), gQKV(8, 12, NB), gKV(8, 8, NB), gONE(8, 4, NB), gHID(8, 16, NB);
    dim3 gLN(32, NB), gATT(16, 4, NB), gDW(4, 32, NB);

    // ---- q branch ----
    mm_tc<3,1,0><<<gC, 256, MM_SMEM>>>(wbf+WC3, wbf+WC3+SP3, aop, nullptr, nullptr, 0,
        qbr, nullptr, nullptr, nullptr, nullptr, nullptr, 2304, 256, 256, 0, 0);
    ln_kernel<<<gLN, 256>>>(qbr, lnq1_w, lnq1_b, blnh, blnl);
    mm_tc<0,0,1><<<gQKV, 256, MM_SMEM>>>(wbf+WSAQ, wbf+WSAQ+SPQKV, nullptr, blnh, blnl, 256,
        nullptr, nullptr, bqk, bqk + 4194304, bvh, bvl, 256, 0, 512, 3, 8);
    attn_mma<<<gATT, 128, ATT_SMEM>>>(bqk, bqk + 4194304, 512,
        bqk + 256, bqk + 4194304 + 256, 512, bvh, bvl, batth, battl);
    mm_tc<0,0,1><<<gC, 256, MM_SMEM>>>(wbf+WSAQP, wbf+WSAQP+SPCC, nullptr, batth, battl, 256,
        qbr, qbr, nullptr, nullptr, nullptr, nullptr, 256, 0, 256, 0, 0);

    // ---- kv branch ----
    mm_tc<5,2,0><<<gC, 256, MM_SMEM>>>(wbf+WC5, wbf+WC5+SP5, dop, nullptr, nullptr, 0,
        kvbr, nullptr, nullptr, nullptr, nullptr, nullptr, 6400, 256, 256, 0, 0);
    ln_kernel<<<gLN, 256>>>(kvbr, lnkv1_w, lnkv1_b, blnh, blnl);
    mm_tc<0,0,1><<<gQKV, 256, MM_SMEM>>>(wbf+WSAKV, wbf+WSAKV+SPQKV, nullptr, blnh, blnl, 256,
        nullptr, nullptr, bqk, bqk + 4194304, bvh, bvl, 256, 0, 512, 3, 8);
    attn_mma<<<gATT, 128, ATT_SMEM>>>(bqk, bqk + 4194304, 512,
        bqk + 256, bqk + 4194304 + 256, 512, bvh, bvl, batth, battl);
    mm_tc<0,0,1><<<gC, 256, MM_SMEM>>>(wbf+WSAKVP, wbf+WSAKVP+SPCC, nullptr, batth, battl, 256,
        kvbr, kvbr, nullptr, nullptr, nullptr, nullptr, 256, 0, 256, 0, 0);

    // ---- cross attention ----
    ln_kernel<<<gLN, 256>>>(qbr, lnq2_w, lnq2_b, blnh, blnl);
    mm_tc<0,0,1><<<gONE, 256, MM_SMEM>>>(wbf+WCAQ, wbf+WCAQ+SPCC, nullptr, blnh, blnl, 256,
        nullptr, nullptr, bqk, bqk + 2097152, nullptr, nullptr, 256, 0, 256, 1, 0);
    ln_kernel<<<gLN, 256>>>(kvbr, lnkv2_w, lnkv2_b, blnh, blnl);
    mm_tc<0,0,1><<<gKV, 256, MM_SMEM>>>(wbf+WCAKV, wbf+WCAKV+SPKV, nullptr, blnh, blnl, 256,
        nullptr, nullptr, bqk + 4194304, bqk + 6291456, bvh, bvl, 256, 0, 256, 3, 4);
    attn_mma<<<gATT, 128, ATT_SMEM>>>(bqk, bqk + 2097152, 256,
        bqk + 4194304, bqk + 6291456, 256, bvh, bvl, batth, battl);
    mm_tc<0,0,1><<<gC, 256, MM_SMEM>>>(wbf+WCAP, wbf+WCAP+SPCC, nullptr, batth, battl, 256,
        out, qbr, nullptr, nullptr, nullptr, nullptr, 256, 0, 256, 0, 0);

    // ---- LeFF ----
    ln_kernel<<<gLN, 256>>>(out, lnffn_w, lnffn_b, blnh, blnl);
    mm_tc<0,0,1><<<gHID, 256, MM_SMEM>>>(wbf+WLIN, wbf+WLIN+SPLF, nullptr, blnh, blnl, 256,
        h1, nullptr, nullptr, nullptr, nullptr, nullptr, 256, 0, 1024, 0, 0);
    dwconv_gelu_tok<<<gDW, 256>>>(h1, leff_dw, dwh, dwl);
    mm_tc<0,0,1><<<gC, 256, MM_SMEM>>>(wbf+WLOUT, wbf+WLOUT+SPLF, nullptr, dwh, dwl, 1024,
        out, out, nullptr, nullptr, nullptr, nullptr, 1024, 0, 256, 0, 0);
}

// round 16
// speedup vs baseline: 1.0238x; 1.0238x over previous
#include <cuda_runtime.h>
#include <cuda_bf16.h>
#include <math.h>
#include <stdint.h>

#define NB 8
#define C 256
#define HW 1024
#define HIDDEN 1024

__device__ float g_qbranch[NB*C*HW];
__device__ float g_kvbranch[NB*C*HW];
__device__ float g_h1[NB*HIDDEN*HW];
__device__ float g_h2[NB*HIDDEN*HW];
__device__ __align__(256) __nv_bfloat16 g_wbf[7100000];
__device__ __align__(256) __nv_bfloat16 g_bln[4194304];
__device__ __align__(256) __nv_bfloat16 g_bqk[8388608];
__device__ __align__(256) __nv_bfloat16 g_bv[4194304];
__device__ __align__(256) __nv_bfloat16 g_batt[4194304];

#define WC3    0
#define SP3    589824
#define WC5    1179648
#define SP5    1638400
#define WSAQ   4456448
#define SPQKV  196608
#define WSAKV  4849664
#define WSAQP  5242880
#define SPCC   65536
#define WSAKVP 5373952
#define WCAQ   5505024
#define WCAKV  5636096
#define SPKV   131072
#define WCAP   5898240
#define WLIN   6029312
#define SPLF   262144
#define WLOUT  6553600

// ---------------- helpers ----------------
__device__ __forceinline__ uint32_t smem_u32(const void* p) {
    uint32_t a;
    asm("{ .reg .u64 t; cvta.to.shared.u64 t, %1; cvt.u32.u64 %0, t; }" : "=r"(a) : "l"(p));
    return a;
}
__device__ __forceinline__ void cp16(void* dst, const void* src) {
    unsigned d = (unsigned)__cvta_generic_to_shared(dst);
    asm volatile("cp.async.ca.shared.global [%0], [%1], 16;" :: "r"(d), "l"(src));
}
__device__ __forceinline__ void cp_commit() { asm volatile("cp.async.commit_group;" ::: "memory"); }
__device__ __forceinline__ void cp_wait0()  { asm volatile("cp.async.wait_group 0;" ::: "memory"); }

__device__ __forceinline__ void ldmx4(uint32_t* r, uint32_t addr) {
    asm volatile("ldmatrix.sync.aligned.m8n8.x4.shared.b16 {%0,%1,%2,%3}, [%4];"
        : "=r"(r[0]), "=r"(r[1]), "=r"(r[2]), "=r"(r[3]) : "r"(addr));
}
__device__ __forceinline__ void mma16816(float* c, const uint32_t* a, const uint32_t* b) {
    asm volatile("mma.sync.aligned.m16n8k16.row.col.f32.bf16.bf16.f32 "
        "{%0,%1,%2,%3}, {%4,%5,%6,%7}, {%8,%9}, {%0,%1,%2,%3};"
        : "+f"(c[0]), "+f"(c[1]), "+f"(c[2]), "+f"(c[3])
        : "r"(a[0]), "r"(a[1]), "r"(a[2]), "r"(a[3]), "r"(b[0]), "r"(b[1]));
}
__device__ __forceinline__ unsigned pkbf(float a, float b) {
    __nv_bfloat16 ha = __float2bfloat16(a), hb = __float2bfloat16(b);
    return ((unsigned)__bfloat16_as_ushort(hb) << 16) | __bfloat16_as_ushort(ha);
}
__device__ __forceinline__ void splitpk(float a, float b, unsigned& hi, unsigned& lo) {
    __nv_bfloat16 ha = __float2bfloat16(a), hb = __float2bfloat16(b);
    hi = ((unsigned)__bfloat16_as_ushort(hb) << 16) | __bfloat16_as_ushort(ha);
    lo = pkbf(a - __bfloat162float(ha), b - __bfloat162float(hb));
}

// =====================================================================
// mma.sync GEMM / implicit conv. Tile 128(pix) x 128(oc), fragment-pipelined.
// stage (64K): AH 16K | AL 16K | BH 16K | BL 16K, x2 stages.
// ABF=0: act fp32 chanmaj (KW taps); ABF=1: pre-split bf16 tokmaj.
// outmode 0: fp32 chanmaj (+addp); 1: bf16 tokmaj; 2: bf16 chanmaj;
// 3: y<ysplit -> tokmaj, else chanmaj
// =====================================================================
struct Frag {
    uint32_t aH[2][4], aL[2][4];
    uint32_t bH[8][2], bL[8][2];
};

template<int KW, int PAD, int ABF>
__global__ __launch_bounds__(256, 1) void mm_tc(
    const __nv_bfloat16* __restrict__ whi, const __nv_bfloat16* __restrict__ wlo,
    const float* __restrict__ act,
    const __nv_bfloat16* __restrict__ ahi, const __nv_bfloat16* __restrict__ alo, int arow,
    float* __restrict__ outp, const float* __restrict__ addp,
    __nv_bfloat16* __restrict__ obhi, __nv_bfloat16* __restrict__ oblo,
    __nv_bfloat16* __restrict__ vbhi, __nv_bfloat16* __restrict__ vblo,
    int K, int SA, int Cout, int outmode, int ysplit)
{
    extern __shared__ char sm[];
    int tid = threadIdx.x;
    int pixbase = blockIdx.x * 128;
    int ocbase = blockIdx.y * 128;
    int bimg = blockIdx.z;
    int w = tid >> 5, lane = tid & 31;
    int m0 = (w >> 1) * 32;
    int n0 = (w & 1) * 64;
    uint32_t sbase = smem_u32(sm);

    float acc[2][8][4] = {};
    int apix = tid & 127, ahalf = tid >> 7;

    auto fetchA = [&](int kk, float* v) {
        if (KW == 0) {
            const float* p = act + ((size_t)bimg * SA + kk + ahalf * 32) * 1024 + pixbase + apix;
            #pragma unroll
            for (int i = 0; i < 32; i++) v[i] = p[(size_t)i * 1024];
        } else {
            int kbase = kk + ahalf * 32;
            int tap = kbase >> 8, ic0 = kbase & 255;
            int dy = tap / KW - PAD, dx = tap % KW - PAD;
            int p = pixbase + apix;
            int iy = (p >> 5) + dy, ix = (p & 31) + dx;
            bool ok = ((unsigned)iy < 32u) && ((unsigned)ix < 32u);
            const float* src = act + ((size_t)bimg * 256 + ic0) * 1024 + (iy << 5) + ix;
            #pragma unroll
            for (int i = 0; i < 32; i++) v[i] = ok ? src[(size_t)i * 1024] : 0.f;
        }
    };
    auto storeA = [&](int st, const float* v) {
        char* AH = sm + st * 65536;
        char* AL = AH + 16384;
        #pragma unroll
        for (int gi = 0; gi < 4; gi++) {
            int g = ahalf * 4 + gi;
            unsigned hh[4], ll[4];
            #pragma unroll
            for (int m = 0; m < 4; m++)
                splitpk(v[gi * 8 + 2 * m], v[gi * 8 + 2 * m + 1], hh[m], ll[m]);
            unsigned off = apix * 128 + ((g ^ (apix & 7)) << 4);
            *(uint4*)(AH + off) = make_uint4(hh[0], hh[1], hh[2], hh[3]);
            *(uint4*)(AL + off) = make_uint4(ll[0], ll[1], ll[2], ll[3]);
        }
    };
    auto loadAbf = [&](int st, int kk) {
        char* base = sm + st * 65536;
        #pragma unroll
        for (int i = 0; i < 8; i++) {
            int idx = tid + i * 256;
            int plane = idx >> 10, r = idx & 1023;
            int pix = r >> 3, g = r & 7;
            const __nv_bfloat16* src = (plane ? alo : ahi)
                + ((size_t)bimg * 1024 + pixbase + pix) * arow + kk + g * 8;
            unsigned off = pix * 128 + ((g ^ (pix & 7)) << 4);
            cp16(base + plane * 16384 + off, src);
        }
    };
    auto loadB = [&](int st, int kk) {
        char* base = sm + st * 65536 + 32768;
        #pragma unroll
        for (int i = 0; i < 8; i++) {
            int idx = tid + i * 256;
            int plane = idx >> 10, r = idx & 1023;
            int oc = r >> 3, g = r & 7;
            const __nv_bfloat16* src = (plane ? wlo : whi) + (size_t)(ocbase + oc) * K + kk + g * 8;
            unsigned off = oc * 128 + ((g ^ (oc & 7)) << 4);
            cp16(base + plane * 16384 + off, src);
        }
    };

    auto ldfrags = [&](uint32_t AH, uint32_t AL, uint32_t BH, uint32_t BL, int ks, Frag& F) {
        int kg = ks * 2;
        #pragma unroll
        for (int ms = 0; ms < 2; ms++) {
            int sel = lane >> 3;
            int row = m0 + ms * 16 + (sel & 1) * 8 + (lane & 7);
            int g = kg + (sel >> 1);
            unsigned off = row * 128 + ((g ^ (row & 7)) << 4);
            ldmx4(F.aH[ms], AH + off);
            ldmx4(F.aL[ms], AL + off);
        }
        #pragma unroll
        for (int nj = 0; nj < 4; nj++) {
            int j2 = lane >> 4, half = (lane >> 3) & 1;
            int oc = n0 + (nj * 2 + j2) * 8 + (lane & 7);
            int g = kg + half;
            unsigned off = oc * 128 + ((g ^ (oc & 7)) << 4);
            uint32_t t[4];
            ldmx4(t, BH + off);
            F.bH[nj*2][0] = t[0]; F.bH[nj*2][1] = t[1]; F.bH[nj*2+1][0] = t[2]; F.bH[nj*2+1][1] = t[3];
            ldmx4(t, BL + off);
            F.bL[nj*2][0] = t[0]; F.bL[nj*2][1] = t[1]; F.bL[nj*2+1][0] = t[2]; F.bL[nj*2+1][1] = t[3];
        }
    };
    auto domma = [&](Frag& F) {
        #pragma unroll
        for (int ms = 0; ms < 2; ms++)
            #pragma unroll
            for (int ns = 0; ns < 8; ns++) {
                mma16816(acc[ms][ns], F.aH[ms], F.bH[ns]);
                mma16816(acc[ms][ns], F.aH[ms], F.bL[ns]);
                mma16816(acc[ms][ns], F.aL[ms], F.bH[ns]);
            }
    };
    auto compute = [&](int st) {
        uint32_t AH = sbase + st * 65536, AL = AH + 16384;
        uint32_t BH = AH + 32768, BL = AH + 49152;
        Frag F0, F1;
        ldfrags(AH, AL, BH, BL, 0, F0);
        ldfrags(AH, AL, BH, BL, 1, F1);
        domma(F0);
        ldfrags(AH, AL, BH, BL, 2, F0);
        domma(F1);
        ldfrags(AH, AL, BH, BL, 3, F1);
        domma(F0);
        domma(F1);
    };

    int nk = K >> 6;
    if (ABF) {
        loadB(0, 0); loadAbf(0, 0);
        cp_commit();
        cp_wait0();
        __syncthreads();
        for (int kt = 0; kt < nk; kt++) {
            int st = kt & 1;
            bool more = (kt + 1) < nk;
            if (more) {
                loadB(st ^ 1, (kt + 1) << 6);
                loadAbf(st ^ 1, (kt + 1) << 6);
                cp_commit();
            }
            compute(st);
            if (more) cp_wait0();
            __syncthreads();
        }
    } else {
        float v[32];
        loadB(0, 0); cp_commit();
        fetchA(0, v); storeA(0, v);
        cp_wait0();
        __syncthreads();
        for (int kt = 0; kt < nk; kt++) {
            int st = kt & 1;
            bool more = (kt + 1) < nk;
            if (more) {
                loadB(st ^ 1, (kt + 1) << 6); cp_commit();
                fetchA((kt + 1) << 6, v);
            }
            compute(st);
            if (more) {
                storeA(st ^ 1, v);
                cp_wait0();
            }
            __syncthreads();
        }
    }

    int outm = outmode;
    int ocb = ocbase;
    __nv_bfloat16 *ph = obhi, *pl = oblo;
    if (outmode == 3) {
        if ((int)blockIdx.y < ysplit) outm = 1;
        else { outm = 2; ph = vbhi; pl = vblo; ocb = (blockIdx.y - ysplit) * 128; }
    }

    float* T = (float*)sm;   // [128][132]
    if (outm == 1) {
        #pragma unroll
        for (int ms = 0; ms < 2; ms++)
            #pragma unroll
            for (int ns = 0; ns < 8; ns++)
                #pragma unroll
                for (int e = 0; e < 4; e++) {
                    int pix = m0 + ms * 16 + (lane >> 2) + (e >> 1) * 8;
                    int oc  = n0 + ns * 8 + (lane & 3) * 2 + (e & 1);
                    T[pix * 132 + oc] = acc[ms][ns][e];
                }
        __syncthreads();
        #pragma unroll
        for (int it = 0; it < 16; it++) {
            int f = it * 256 + tid;
            int pix = f >> 5, o4 = (f & 31) * 4;
            float4 vv = *(float4*)&T[pix * 132 + o4];
            unsigned h0, l0, h1, l1;
            splitpk(vv.x, vv.y, h0, l0);
            splitpk(vv.z, vv.w, h1, l1);
            size_t idx = ((size_t)bimg * 1024 + pixbase + pix) * Cout + ocbase + o4;
            *(uint2*)(ph + idx) = make_uint2(h0, h1);
            *(uint2*)(pl + idx) = make_uint2(l0, l1);
        }
    } else {
        #pragma unroll
        for (int ms = 0; ms < 2; ms++)
            #pragma unroll
            for (int ns = 0; ns < 8; ns++)
                #pragma unroll
                for (int e = 0; e < 4; e++) {
                    int pix = m0 + ms * 16 + (lane >> 2) + (e >> 1) * 8;
                    int oc  = n0 + ns * 8 + (lane & 3) * 2 + (e & 1);
                    T[oc * 132 + pix] = acc[ms][ns][e];
                }
        __syncthreads();
        #pragma unroll
        for (int it = 0; it < 16; it++) {
            int f = it * 256 + tid;
            int oc = f >> 5, p4 = (f & 31) * 4;
            float4 vv = *(float4*)&T[oc * 132 + p4];
            if (outm == 0) {
                size_t go = ((size_t)bimg * Cout + ocb + oc) * 1024 + pixbase + p4;
                if (addp) {
                    float4 a = *(const float4*)(addp + go);
                    vv.x += a.x; vv.y += a.y; vv.z += a.z; vv.w += a.w;
                }
                *(float4*)(outp + go) = vv;
            } else {
                unsigned h0, l0, h1, l1;
                splitpk(vv.x, vv.y, h0, l0);
                splitpk(vv.z, vv.w, h1, l1);
                size_t idx = ((size_t)bimg * 256 + ocb + oc) * 1024 + pixbase + p4;
                *(uint2*)(ph + idx) = make_uint2(h0, h1);
                *(uint2*)(pl + idx) = make_uint2(l0, l1);
            }
        }
    }
}

// ---------------- fused weight prep ----------------
__global__ __launch_bounds__(256) void prep_w(
    __nv_bfloat16* __restrict__ wb,
    const float* w3, const float* w5,
    const float* saqk, const float* sakvk,
    const float* saqp, const float* sakvp,
    const float* caq, const float* cak, const float* cav, const float* cap,
    const float* lin, const float* lout)
{
    int i = blockIdx.x * 256 + threadIdx.x;
    float v; size_t dh, dl;
    if (i < 589824) {
        int j = i;
        int oc = j / (9*256); int r = j - oc*9*256; int tap = r >> 8, ic = r & 255;
        v = w3[((size_t)(oc*256+ic))*9 + tap]; dh = WC3 + j; dl = dh + SP3;
    } else if (i < 2228224) {
        int j = i - 589824;
        int oc = j / (25*256); int r = j - oc*25*256; int tap = r >> 8, ic = r & 255;
        v = w5[((size_t)(oc*256+ic))*25 + tap]; dh = WC5 + j; dl = dh + SP5;
    } else if (i < 2424832) { int j = i - 2228224; v = saqk[j];  dh = WSAQ + j;  dl = dh + SPQKV; }
    else if (i < 2621440) { int j = i - 2424832; v = sakvk[j]; dh = WSAKV + j; dl = dh + SPQKV; }
    else if (i < 2686976) { int j = i - 2621440; v = saqp[j];  dh = WSAQP + j; dl = dh + SPCC; }
    else if (i < 2752512) { int j = i - 2686976; v = sakvp[j]; dh = WSAKVP + j; dl = dh + SPCC; }
    else if (i < 2818048) { int j = i - 2752512; v = caq[j];   dh = WCAQ + j;  dl = dh + SPCC; }
    else if (i < 2883584) { int j = i - 2818048; v = cak[j];   dh = WCAKV + j; dl = dh + SPKV; }
    else if (i < 2949120) { int j = i - 2883584; v = cav[j];   dh = WCAKV + 65536 + j; dl = dh + SPKV; }
    else if (i < 3014656) { int j = i - 2949120; v = cap[j];   dh = WCAP + j;  dl = dh + SPCC; }
    else if (i < 3276800) { int j = i - 3014656; v = lin[j];   dh = WLIN + j;  dl = dh + SPLF; }
    else if (i < 3538944) { int j = i - 3276800; v = lout[j];  dh = WLOUT + j; dl = dh + SPLF; }
    else return;
    __nv_bfloat16 h = __float2bfloat16(v);
    wb[dh] = h;
    wb[dl] = __float2bfloat16(v - __bfloat162float(h));
}

// ---------------- layernorm: chanmaj fp32 -> tokmaj bf16 hi/lo ----------------
__global__ __launch_bounds__(256) void ln_kernel(
    const float* __restrict__ x, const float* __restrict__ w,
    const float* __restrict__ bias,
    __nv_bfloat16* __restrict__ bhi, __nv_bfloat16* __restrict__ blo)
{
    int b = blockIdx.y;
    int n0 = blockIdx.x * 32;
    int nx = threadIdx.x & 31;
    int cg = threadIdx.x >> 5;
    const float* xb = x + (size_t)b * C * HW + n0 + nx;
    float v[32];
    float s = 0.f, ss = 0.f;
    #pragma unroll
    for (int i = 0; i < 32; i++) {
        float t = xb[(size_t)(cg * 32 + i) * HW];
        v[i] = t; s += t; ss += t * t;
    }
    __shared__ float rs[8][32], rss[8][32];
    rs[cg][nx] = s; rss[cg][nx] = ss;
    __syncthreads();
    float tot = 0.f, tot2 = 0.f;
    #pragma unroll
    for (int g = 0; g < 8; g++) { tot += rs[g][nx]; tot2 += rss[g][nx]; }
    float mu = tot * (1.f / 256.f);
    float var = tot2 * (1.f / 256.f) - mu * mu;
    float rstd = rsqrtf(var + 1e-5f);
    size_t orow = ((size_t)b * 1024 + n0 + nx) * 256 + cg * 32;
    #pragma unroll
    for (int i4 = 0; i4 < 4; i4++) {
        unsigned hh[4], ll[4];
        #pragma unroll
        for (int j = 0; j < 4; j++) {
            int i = i4 * 8 + j * 2;
            int c = cg * 32 + i;
            float a = (v[i]   - mu) * rstd * w[c]   + bias[c];
            float d = (v[i+1] - mu) * rstd * w[c+1] + bias[c+1];
            splitpk(a, d, hh[j], ll[j]);
        }
        *(uint4*)(bhi + orow + i4 * 8) = make_uint4(hh[0], hh[1], hh[2], hh[3]);
        *(uint4*)(blo + orow + i4 * 8) = make_uint4(ll[0], ll[1], ll[2], ll[3]);
    }
}

// ---------------- tensor-core flash attention (pre-split bf16) ----------------
__global__ __launch_bounds__(128) void attn_mma(
    const __nv_bfloat16* __restrict__ qhi, const __nv_bfloat16* __restrict__ qlo, int qrow,
    const __nv_bfloat16* __restrict__ khi, const __nv_bfloat16* __restrict__ klo, int krow,
    const __nv_bfloat16* __restrict__ vhi, const __nv_bfloat16* __restrict__ vlo,
    __nv_bfloat16* __restrict__ ohi, __nv_bfloat16* __restrict__ olo)
{
    extern __shared__ char sm[];
    uint32_t sbase = smem_u32(sm);
    int tid = threadIdx.x;
    int w = tid >> 5, lane = tid & 31;
    int q0 = blockIdx.x * 64;
    int hoff = blockIdx.y * 64;
    int bimg = blockIdx.z;
    int m0 = w * 16;

    auto loadQ = [&]() {
        #pragma unroll
        for (int i = 0; i < 8; i++) {
            int idx = tid + i * 128;
            int plane = idx >> 9, r = idx & 511;
            int q = r >> 3, g = r & 7;
            const __nv_bfloat16* src = (plane ? qlo : qhi)
                + ((size_t)bimg * 1024 + q0 + q) * qrow + hoff + g * 8;
            unsigned off = q * 128 + ((g ^ (q & 7)) << 4);
            cp16(sm + plane * 8192 + off, src);
        }
    };
    auto loadKV = [&](int st, int c0) {
        char* base = sm + 16384 + st * 32768;
        #pragma unroll
        for (int i = 0; i < 16; i++) {
            int idx = tid + i * 128;
            int which = idx >> 10;
            int plane = (idx >> 9) & 1;
            int r = idx & 511;
            int row = r >> 3, g = r & 7;
            const __nv_bfloat16* src;
            if (which == 0)
                src = (plane ? klo : khi) + ((size_t)bimg * 1024 + c0 + row) * krow + hoff + g * 8;
            else
                src = (plane ? vlo : vhi) + ((size_t)bimg * 256 + hoff + row) * 1024 + c0 + g * 8;
            unsigned off = row * 128 + ((g ^ (row & 7)) << 4);
            cp16(base + which * 16384 + plane * 8192 + off, src);
        }
    };

    loadQ();
    loadKV(0, 0);
    cp_commit();

    float oacc[8][4] = {};
    float mrun[2], lrun[2];
    mrun[0] = mrun[1] = -1e30f;
    lrun[0] = lrun[1] = 0.f;

    cp_wait0();
    __syncthreads();

    const uint32_t QH = sbase, QL = sbase + 8192;
    for (int c = 0; c < 16; c++) {
        int st = c & 1;
        bool more = (c + 1) < 16;
        if (more) { loadKV(st ^ 1, (c + 1) * 64); cp_commit(); }

        uint32_t KB = sbase + 16384 + st * 32768;
        uint32_t KH = KB, KL = KB + 8192, VH = KB + 16384, VL = KB + 24576;

        float s[8][4] = {};
        #pragma unroll
        for (int ks4 = 0; ks4 < 4; ks4++) {
            int kg = ks4 * 2;
            uint32_t aH[4], aL[4];
            {
                int sel = lane >> 3;
                int row = m0 + (sel & 1) * 8 + (lane & 7);
                int g = kg + (sel >> 1);
                unsigned off = row * 128 + ((g ^ (row & 7)) << 4);
                ldmx4(aH, QH + off);
                ldmx4(aL, QL + off);
            }
            #pragma unroll
            for (int nj = 0; nj < 4; nj++) {
                int j2 = lane >> 4, half = (lane >> 3) & 1;
                int kv = (nj * 2 + j2) * 8 + (lane & 7);
                int g = kg + half;
                unsigned off = kv * 128 + ((g ^ (kv & 7)) << 4);
                uint32_t t[4], bh0[2], bh1[2], bl0[2], bl1[2];
                ldmx4(t, KH + off);
                bh0[0] = t[0]; bh0[1] = t[1]; bh1[0] = t[2]; bh1[1] = t[3];
                ldmx4(t, KL + off);
                bl0[0] = t[0]; bl0[1] = t[1]; bl1[0] = t[2]; bl1[1] = t[3];
                mma16816(s[nj*2], aH, bh0);   mma16816(s[nj*2+1], aH, bh1);
                mma16816(s[nj*2], aH, bl0);   mma16816(s[nj*2+1], aH, bl1);
                mma16816(s[nj*2], aL, bh0);   mma16816(s[nj*2+1], aL, bh1);
            }
        }
        #pragma unroll
        for (int e = 0; e < 8; e++)
            #pragma unroll
            for (int j = 0; j < 4; j++) s[e][j] *= 0.125f;

        #pragma unroll
        for (int r = 0; r < 2; r++) {
            int e0 = r * 2;
            float mx = -1e30f;
            #pragma unroll
            for (int e = 0; e < 8; e++)
                mx = fmaxf(mx, fmaxf(s[e][e0], s[e][e0+1]));
            mx = fmaxf(mx, __shfl_xor_sync(0xffffffffu, mx, 1));
            mx = fmaxf(mx, __shfl_xor_sync(0xffffffffu, mx, 2));
            float mnew = fmaxf(mrun[r], mx);
            float corr = __expf(mrun[r] - mnew);
            float rsum = 0.f;
            #pragma unroll
            for (int e = 0; e < 8; e++) {
                float p0 = __expf(s[e][e0] - mnew);
                float p1 = __expf(s[e][e0+1] - mnew);
                s[e][e0] = p0; s[e][e0+1] = p1;
                rsum += p0 + p1;
            }
            rsum += __shfl_xor_sync(0xffffffffu, rsum, 1);
            rsum += __shfl_xor_sync(0xffffffffu, rsum, 2);
            lrun[r] = lrun[r] * corr + rsum;
            mrun[r] = mnew;
            #pragma unroll
            for (int e = 0; e < 8; e++) {
                oacc[e][e0] *= corr; oacc[e][e0+1] *= corr;
            }
        }

        #pragma unroll
        for (int ks4 = 0; ks4 < 4; ks4++) {
            int e = ks4 * 2;
            uint32_t aPh[4], aPl[4];
            splitpk(s[e][0],   s[e][1],   aPh[0], aPl[0]);
            splitpk(s[e][2],   s[e][3],   aPh[1], aPl[1]);
            splitpk(s[e+1][0], s[e+1][1], aPh[2], aPl[2]);
            splitpk(s[e+1][2], s[e+1][3], aPh[3], aPl[3]);
            int kg = ks4 * 2;
            #pragma unroll
            for (int nj = 0; nj < 4; nj++) {
                int j2 = lane >> 4, half = (lane >> 3) & 1;
                int d = (nj * 2 + j2) * 8 + (lane & 7);
                int g = kg + half;
                unsigned off = d * 128 + ((g ^ (d & 7)) << 4);
                uint32_t t[4], bh0[2], bh1[2], bl0[2], bl1[2];
                ldmx4(t, VH + off);
                bh0[0] = t[0]; bh0[1] = t[1]; bh1[0] = t[2]; bh1[1] = t[3];
                ldmx4(t, VL + off);
                bl0[0] = t[0]; bl0[1] = t[1]; bl1[0] = t[2]; bl1[1] = t[3];
                mma16816(oacc[nj*2], aPh, bh0);   mma16816(oacc[nj*2+1], aPh, bh1);
                mma16816(oacc[nj*2], aPh, bl0);   mma16816(oacc[nj*2+1], aPh, bl1);
                mma16816(oacc[nj*2], aPl, bh0);   mma16816(oacc[nj*2+1], aPl, bh1);
            }
        }
        if (more) cp_wait0();
        __syncthreads();
    }

    float li[2] = {1.f / lrun[0], 1.f / lrun[1]};
    #pragma unroll
    for (int nt = 0; nt < 8; nt++)
        #pragma unroll
        for (int r = 0; r < 2; r++) {
            int q = m0 + (lane >> 2) + r * 8;
            int d0 = nt * 8 + (lane & 3) * 2;
            unsigned hi, lo;
            splitpk(oacc[nt][2*r] * li[r], oacc[nt][2*r+1] * li[r], hi, lo);
            size_t idx = ((size_t)bimg * 1024 + q0 + q) * 256 + hoff + d0;
            *(unsigned*)(ohi + idx) = hi;
            *(unsigned*)(olo + idx) = lo;
        }
}

// ---------------- depthwise 3x3 + GELU -> tokmaj bf16 hi/lo ----------------
__global__ __launch_bounds__(256) void dwconv_gelu_tok(
    const float* __restrict__ X, const float* __restrict__ W,
    __nv_bfloat16* __restrict__ bhi, __nv_bfloat16* __restrict__ blo)
{
    __shared__ float tile[32][10][32];
    __shared__ float wsm[32][9];
    int tid = threadIdx.x;
    int p0 = blockIdx.x * 256;
    int c0 = blockIdx.y * 32;
    int b = blockIdx.z;
    int r0 = p0 >> 5;

    for (int e = tid; e < 288; e += 256) {
        int c = e / 9, k = e - c * 9;
        wsm[c][k] = W[(size_t)(c0 + c) * 9 + k];
    }
    for (int e = tid; e < 32 * 10 * 32; e += 256) {
        int c = e / 320, rr = e - c * 320;
        int lr = rr >> 5, col = rr & 31;
        int gr = r0 + lr - 1;
        tile[c][lr][col] = ((unsigned)gr < 32u)
            ? X[((size_t)(b * 1024 + c0 + c)) * 1024 + (gr << 5) + col] : 0.f;
    }
    __syncthreads();

    int p = p0 + tid;
    int ly = (p >> 5) - r0 + 1;
    int x = p & 31;
    unsigned hh[16], ll[16];
    float prev = 0.f;
    #pragma unroll
    for (int c = 0; c < 32; c++) {
        float acc = 0.f;
        #pragma unroll
        for (int dy = 0; dy < 3; dy++) {
            #pragma unroll
            for (int dx = 0; dx < 3; dx++) {
                int ix = x + dx - 1;
                float vv = ((unsigned)ix < 32u) ? tile[c][ly + dy - 1][ix] : 0.f;
                acc += wsm[c][dy * 3 + dx] * vv;
            }
        }
        float g = 0.5f * acc * (1.f + erff(acc * 0.70710678118654752440f));
        if (c & 1) splitpk(prev, g, hh[c >> 1], ll[c >> 1]);
        prev = g;
    }
    size_t orow = ((size_t)b * 1024 + p) * 1024 + c0;
    #pragma unroll
    for (int q = 0; q < 4; q++) {
        *(uint4*)(bhi + orow + q * 8) = make_uint4(hh[q*4], hh[q*4+1], hh[q*4+2], hh[q*4+3]);
        *(uint4*)(blo + orow + q * 8) = make_uint4(ll[q*4], ll[q*4+1], ll[q*4+2], ll[q*4+3]);
    }
}

// ---------------- host ----------------
extern "C" void kernel_launch(void* const* d_in, const int* in_sizes, int n_in,
                              void* d_out, int out_size)
{
    const float* aop      = (const float*)d_in[0];
    const float* dop      = (const float*)d_in[1];
    const float* w_qconv  = (const float*)d_in[2];
    const float* w_kvconv = (const float*)d_in[3];
    const float* lnq1_w   = (const float*)d_in[4];
    const float* lnq1_b   = (const float*)d_in[5];
    const float* lnkv1_w  = (const float*)d_in[6];
    const float* lnkv1_b  = (const float*)d_in[7];
    const float* lnq2_w   = (const float*)d_in[8];
    const float* lnq2_b   = (const float*)d_in[9];
    const float* lnkv2_w  = (const float*)d_in[10];
    const float* lnkv2_b  = (const float*)d_in[11];
    const float* lnffn_w  = (const float*)d_in[12];
    const float* lnffn_b  = (const float*)d_in[13];
    const float* saq_qkv  = (const float*)d_in[14];
    const float* saq_proj = (const float*)d_in[15];
    const float* sakv_qkv = (const float*)d_in[16];
    const float* sakv_proj= (const float*)d_in[17];
    const float* ca_q     = (const float*)d_in[18];
    const float* ca_k     = (const float*)d_in[19];
    const float* ca_v     = (const float*)d_in[20];
    const float* ca_proj  = (const float*)d_in[21];
    const float* leff_in  = (const float*)d_in[22];
    const float* leff_dw  = (const float*)d_in[23];
    const float* leff_out = (const float*)d_in[24];
    float* out = (float*)d_out;

    float *qbr, *kvbr, *h1, *h2;
    __nv_bfloat16 *wbf, *bln, *bqk, *bv, *batt;
    cudaGetSymbolAddress((void**)&qbr,  g_qbranch);
    cudaGetSymbolAddress((void**)&kvbr, g_kvbranch);
    cudaGetSymbolAddress((void**)&h1,   g_h1);
    cudaGetSymbolAddress((void**)&h2,   g_h2);
    cudaGetSymbolAddress((void**)&wbf,  g_wbf);
    cudaGetSymbolAddress((void**)&bln,  g_bln);
    cudaGetSymbolAddress((void**)&bqk,  g_bqk);
    cudaGetSymbolAddress((void**)&bv,   g_bv);
    cudaGetSymbolAddress((void**)&batt, g_batt);

    __nv_bfloat16 *blnh = bln, *blnl = bln + 2097152;
    __nv_bfloat16 *bvh = bv, *bvl = bv + 2097152;
    __nv_bfloat16 *batth = batt, *battl = batt + 2097152;
    __nv_bfloat16 *dwh = (__nv_bfloat16*)h2, *dwl = (__nv_bfloat16*)h2 + 8388608;

    const int MM_SMEM = 131072;
    const int ATT_SMEM = 81920;
    cudaFuncSetAttribute(attn_mma, cudaFuncAttributeMaxDynamicSharedMemorySize, ATT_SMEM);
    cudaFuncSetAttribute(mm_tc<0,0,0>, cudaFuncAttributeMaxDynamicSharedMemorySize, MM_SMEM);
    cudaFuncSetAttribute(mm_tc<0,0,1>, cudaFuncAttributeMaxDynamicSharedMemorySize, MM_SMEM);
    cudaFuncSetAttribute(mm_tc<3,1,0>, cudaFuncAttributeMaxDynamicSharedMemorySize, MM_SMEM);
    cudaFuncSetAttribute(mm_tc<5,2,0>, cudaFuncAttributeMaxDynamicSharedMemorySize, MM_SMEM);

    prep_w<<<13824, 256>>>(wbf, w_qconv, w_kvconv, saq_qkv, sakv_qkv, saq_proj, sakv_proj,
                           ca_q, ca_k, ca_v, ca_proj, leff_in, leff_out);

    dim3 gC(8, 2, NB), gQKV(8, 6, NB), gKV(8, 4, NB), gONE(8, 2, NB), gHID(8, 8, NB);
    dim3 gLN(32, NB), gATT(16, 4, NB), gDW(4, 32, NB);

    // ---- q branch ----
    mm_tc<3,1,0><<<gC, 256, MM_SMEM>>>(wbf+WC3, wbf+WC3+SP3, aop, nullptr, nullptr, 0,
        qbr, nullptr, nullptr, nullptr, nullptr, nullptr, 2304, 256, 256, 0, 0);
    ln_kernel<<<gLN, 256>>>(qbr, lnq1_w, lnq1_b, blnh, blnl);
    mm_tc<0,0,1><<<gQKV, 256, MM_SMEM>>>(wbf+WSAQ, wbf+WSAQ+SPQKV, nullptr, blnh, blnl, 256,
        nullptr, nullptr, bqk, bqk + 4194304, bvh, bvl, 256, 0, 512, 3, 4);
    attn_mma<<<gATT, 128, ATT_SMEM>>>(bqk, bqk + 4194304, 512,
        bqk + 256, bqk + 4194304 + 256, 512, bvh, bvl, batth, battl);
    mm_tc<0,0,1><<<gC, 256, MM_SMEM>>>(wbf+WSAQP, wbf+WSAQP+SPCC, nullptr, batth, battl, 256,
        qbr, qbr, nullptr, nullptr, nullptr, nullptr, 256, 0, 256, 0, 0);

    // ---- kv branch ----
    mm_tc<5,2,0><<<gC, 256, MM_SMEM>>>(wbf+WC5, wbf+WC5+SP5, dop, nullptr, nullptr, 0,
        kvbr, nullptr, nullptr, nullptr, nullptr, nullptr, 6400, 256, 256, 0, 0);
    ln_kernel<<<gLN, 256>>>(kvbr, lnkv1_w, lnkv1_b, blnh, blnl);
    mm_tc<0,0,1><<<gQKV, 256, MM_SMEM>>>(wbf+WSAKV, wbf+WSAKV+SPQKV, nullptr, blnh, blnl, 256,
        nullptr, nullptr, bqk, bqk + 4194304, bvh, bvl, 256, 0, 512, 3, 4);
    attn_mma<<<gATT, 128, ATT_SMEM>>>(bqk, bqk + 4194304, 512,
        bqk + 256, bqk + 4194304 + 256, 512, bvh, bvl, batth, battl);
    mm_tc<0,0,1><<<gC, 256, MM_SMEM>>>(wbf+WSAKVP, wbf+WSAKVP+SPCC, nullptr, batth, battl, 256,
        kvbr, kvbr, nullptr, nullptr, nullptr, nullptr, 256, 0, 256, 0, 0);

    // ---- cross attention ----
    ln_kernel<<<gLN, 256>>>(qbr, lnq2_w, lnq2_b, blnh, blnl);
    mm_tc<0,0,1><<<gONE, 256, MM_SMEM>>>(wbf+WCAQ, wbf+WCAQ+SPCC, nullptr, blnh, blnl, 256,
        nullptr, nullptr, bqk, bqk + 2097152, nullptr, nullptr, 256, 0, 256, 1, 0);
    ln_kernel<<<gLN, 256>>>(kvbr, lnkv2_w, lnkv2_b, blnh, blnl);
    mm_tc<0,0,1><<<gKV, 256, MM_SMEM>>>(wbf+WCAKV, wbf+WCAKV+SPKV, nullptr, blnh, blnl, 256,
        nullptr, nullptr, bqk + 4194304, bqk + 6291456, bvh, bvl, 256, 0, 256, 3, 2);
    attn_mma<<<gATT, 128, ATT_SMEM>>>(bqk, bqk + 2097152, 256,
        bqk + 4194304, bqk + 6291456, 256, bvh, bvl, batth, battl);
    mm_tc<0,0,1><<<gC, 256, MM_SMEM>>>(wbf+WCAP, wbf+WCAP+SPCC, nullptr, batth, battl, 256,
        out, qbr, nullptr, nullptr, nullptr, nullptr, 256, 0, 256, 0, 0);

    // ---- LeFF ----
    ln_kernel<<<gLN, 256>>>(out, lnffn_w, lnffn_b, blnh, blnl);
    mm_tc<0,0,1><<<gHID, 256, MM_SMEM>>>(wbf+WLIN, wbf+WLIN+SPLF, nullptr, blnh, blnl, 256,
        h1, nullptr, nullptr, nullptr, nullptr, nullptr, 256, 0, 1024, 0, 0);
    dwconv_gelu_tok<<<gDW, 256>>>(h1, leff_dw, dwh, dwl);
    mm_tc<0,0,1><<<gC, 256, MM_SMEM>>>(wbf+WLOUT, wbf+WLOUT+SPLF, nullptr, dwh, dwl, 1024,
        out, out, nullptr, nullptr, nullptr, nullptr, 1024, 0, 256, 0, 0);
}